// round 1
// baseline (speedup 1.0000x reference)
#include <cuda_runtime.h>

#define R_N 1000
#define C_N 81
#define NC  80          // foreground classes
#define NEGV (-1e9f)
#define SCORE_T 0.05f
#define IOU_T 0.5f
#define TOPK 100

// ---------------- device scratch (no allocations allowed) ----------------
__device__ float g_scores[NC * R_N];                 // [class-1][row] prob
__device__ float g_boxes[NC * R_N * 4];              // [class-1][row][4] clipped xyxy
__device__ float g_flat[NC * R_N];                   // kept score else NEG (for <100 fallback)
__device__ unsigned long long g_pool[NC * R_N];      // survivor keys
__device__ int g_count;

// ---------------- helpers ----------------
__device__ __forceinline__ unsigned int ord32(float f) {
    unsigned int u = __float_as_uint(f);
    return (u & 0x80000000u) ? ~u : (u | 0x80000000u);
}
__device__ __forceinline__ float unord32(unsigned int u) {
    unsigned int b = (u & 0x80000000u) ? (u ^ 0x80000000u) : ~u;
    return __uint_as_float(b);
}
__device__ __forceinline__ float load_dim(const void* p) {
    int iv = *(const int*)p;
    if (iv > 0 && iv < 1000000) return (float)iv;   // passed as int
    return *(const float*)p;                         // passed as float
}

// descending bitonic sort over shared u64 array, n = power of two
__device__ void bitonic_desc(unsigned long long* a, int n) {
    for (unsigned int k = 2; k <= (unsigned int)n; k <<= 1) {
        for (unsigned int j = k >> 1; j > 0; j >>= 1) {
            for (unsigned int i = threadIdx.x; i < (unsigned int)n; i += blockDim.x) {
                unsigned int l = i ^ j;
                if (l > i) {
                    unsigned long long x = a[i], y = a[l];
                    bool up = ((i & k) == 0);       // descending block
                    if (up ? (x < y) : (x > y)) { a[i] = y; a[l] = x; }
                }
            }
            __syncthreads();
        }
    }
}

// ---------------- kernel 0: init ----------------
__global__ void k_init() {
    int i = blockIdx.x * blockDim.x + threadIdx.x;
    if (i == 0) g_count = 0;
    if (i < NC * R_N) g_flat[i] = NEGV;
}

// ---------------- kernel 1: softmax + decode + clip ----------------
// one warp per proposal row
__global__ void k_decode(const float* __restrict__ logits,
                         const float* __restrict__ reg,
                         const float* __restrict__ props,
                         const void* pw, const void* ph) {
    int row = (blockIdx.x * blockDim.x + threadIdx.x) >> 5;
    int lane = threadIdx.x & 31;
    if (row >= R_N) return;

    float W = load_dim(pw), H = load_dim(ph);
    const float* lg = logits + (size_t)row * C_N;

    float m = -INFINITY;
    for (int i = lane; i < C_N; i += 32) m = fmaxf(m, lg[i]);
    for (int o = 16; o; o >>= 1) m = fmaxf(m, __shfl_xor_sync(0xffffffffu, m, o));

    float s = 0.f;
    for (int i = lane; i < C_N; i += 32) s += expf(lg[i] - m);
    for (int o = 16; o; o >>= 1) s += __shfl_xor_sync(0xffffffffu, s, o);
    float inv = 1.f / s;

    float px1 = props[row * 4 + 0], py1 = props[row * 4 + 1];
    float px2 = props[row * 4 + 2], py2 = props[row * 4 + 3];
    float bw = px2 - px1 + 1.f, bh = py2 - py1 + 1.f;
    float cx = px1 + 0.5f * bw,  cy = py1 + 0.5f * bh;
    const float CLIPV = 4.135166556742356f;   // log(1000/16)

    for (int c = 1 + lane; c < C_N; c += 32) {
        float prob = expf(lg[c] - m) * inv;
        const float* rr = reg + (size_t)row * (C_N * 4) + 4 * c;
        float dx = rr[0] / 10.0f;
        float dy = rr[1] / 10.0f;
        float dw = fminf(rr[2] / 5.0f, CLIPV);
        float dh = fminf(rr[3] / 5.0f, CLIPV);
        float pcx = dx * bw + cx;
        float pcy = dy * bh + cy;
        float pw2 = expf(dw) * bw;
        float ph2 = expf(dh) * bh;
        float x1 = pcx - 0.5f * pw2;
        float y1 = pcy - 0.5f * ph2;
        float x2 = pcx + 0.5f * pw2 - 1.f;
        float y2 = pcy + 0.5f * ph2 - 1.f;
        x1 = fminf(fmaxf(x1, 0.f), W - 1.f);
        x2 = fminf(fmaxf(x2, 0.f), W - 1.f);
        y1 = fminf(fmaxf(y1, 0.f), H - 1.f);
        y2 = fminf(fmaxf(y2, 0.f), H - 1.f);
        int o = (c - 1) * R_N + row;
        g_scores[o] = prob;
        float* ob = g_boxes + (size_t)o * 4;
        ob[0] = x1; ob[1] = y1; ob[2] = x2; ob[3] = y2;
    }
}

// ---------------- kernel 2: per-class greedy NMS (one block per class) ----------------
__global__ void k_nms() {
    int c = blockIdx.x;
    __shared__ unsigned long long skey[1024];
    __shared__ float sx1[1024], sy1[1024], sx2[1024], sy2[1024], sar[1024];
    __shared__ unsigned char srem[1024];
    __shared__ int sM;
    if (threadIdx.x == 0) sM = 0;
    __syncthreads();

    const float* sc = g_scores + (size_t)c * R_N;
    for (int r = threadIdx.x; r < R_N; r += blockDim.x) {
        float v = sc[r];
        if (v > SCORE_T) {
            int p = atomicAdd(&sM, 1);
            skey[p] = ((unsigned long long)ord32(v) << 32) | (unsigned int)(~r);
        }
    }
    __syncthreads();
    int M = sM;
    if (M == 0) return;

    int n = 1; while (n < M) n <<= 1;
    for (int i = M + threadIdx.x; i < n; i += blockDim.x) skey[i] = 0ULL;
    __syncthreads();
    bitonic_desc(skey, n);   // deterministic (score desc, row asc) order

    for (int i = threadIdx.x; i < M; i += blockDim.x) {
        int r = (int)(~(unsigned int)(skey[i] & 0xffffffffu));
        const float* b = g_boxes + ((size_t)c * R_N + r) * 4;
        float x1 = b[0], y1 = b[1], x2 = b[2], y2 = b[3];
        sx1[i] = x1; sy1[i] = y1; sx2[i] = x2; sy2[i] = y2;
        sar[i] = (x2 - x1 + 1.f) * (y2 - y1 + 1.f);
        srem[i] = 0;
    }
    __syncthreads();

    // greedy suppression in sorted order
    for (int i = 0; i < M; i++) {
        if (!srem[i]) {   // uniform: shared value stable since last barrier
            float X1 = sx1[i], Y1 = sy1[i], X2 = sx2[i], Y2 = sy2[i], A = sar[i];
            for (int j = i + 1 + threadIdx.x; j < M; j += blockDim.x) {
                if (!srem[j]) {
                    float ix1 = fmaxf(X1, sx1[j]), iy1 = fmaxf(Y1, sy1[j]);
                    float ix2 = fminf(X2, sx2[j]), iy2 = fminf(Y2, sy2[j]);
                    float iw = fmaxf(ix2 - ix1 + 1.f, 0.f);
                    float ih = fmaxf(iy2 - iy1 + 1.f, 0.f);
                    float inter = iw * ih;
                    float iou = inter / (A + sar[j] - inter);
                    if (iou > IOU_T) srem[j] = 1;
                }
            }
        }
        __syncthreads();
    }

    for (int i = threadIdx.x; i < M; i += blockDim.x) {
        if (!srem[i]) {
            int r = (int)(~(unsigned int)(skey[i] & 0xffffffffu));
            int flat = c * R_N + r;
            float v = sc[r];
            g_flat[flat] = v;
            int p = atomicAdd(&g_count, 1);
            g_pool[p] = ((unsigned long long)ord32(v) << 32) | (unsigned int)(~flat);
        }
    }
}

// ---------------- kernel 3: global top-100 + gather output ----------------
__global__ void k_top(float* __restrict__ out) {
    __shared__ unsigned long long key[4096];
    __shared__ int sidx[1024];
    int tid = threadIdx.x;
    int K = g_count;

    if (K <= 4096) {
        int n = 128; while (n < K) n <<= 1;
        for (int i = tid; i < n; i += blockDim.x) key[i] = (i < K) ? g_pool[i] : 0ULL;
        __syncthreads();
        bitonic_desc(key, n);
        if (K < TOPK && tid == 0) {
            // reproduce top_k tie-break over NEG-filled entries (ascending flat idx)
            int p = K;
            for (int f = 0; f < NC * R_N && p < TOPK; f++)
                if (g_flat[f] == NEGV)
                    key[p++] = ((unsigned long long)ord32(NEGV) << 32) | (unsigned int)(~f);
        }
        __syncthreads();
    } else {
        // robust fallback (not expected to run): iterative argmax selection
        for (int t = 0; t < TOPK; t++) {
            unsigned long long best = 0ULL; int bi = -1;
            for (int i = tid; i < K; i += blockDim.x) {
                unsigned long long v = g_pool[i];
                if (v > best) { best = v; bi = i; }
            }
            key[tid] = best; sidx[tid] = bi;
            __syncthreads();
            for (int o = blockDim.x / 2; o > 0; o >>= 1) {
                if (tid < o && key[tid + o] > key[tid]) {
                    key[tid] = key[tid + o]; sidx[tid] = sidx[tid + o];
                }
                __syncthreads();
            }
            if (tid == 0) {
                key[2048 + t] = key[0];
                if (sidx[0] >= 0) g_pool[sidx[0]] = 0ULL;
            }
            __syncthreads();
        }
        unsigned long long v = (tid < TOPK) ? key[2048 + tid] : 0ULL;
        __syncthreads();
        if (tid < TOPK) key[tid] = v;
        __syncthreads();
    }

    for (int k = tid; k < TOPK; k += blockDim.x) {
        unsigned long long kk = key[k];
        unsigned int flat = ~(unsigned int)(kk & 0xffffffffu);
        float score = unord32((unsigned int)(kk >> 32));
        int c = flat / R_N;
        const float* b = g_boxes + (size_t)flat * 4;
        out[k] = score;
        out[TOPK + 4 * k + 0] = b[0];
        out[TOPK + 4 * k + 1] = b[1];
        out[TOPK + 4 * k + 2] = b[2];
        out[TOPK + 4 * k + 3] = b[3];
        out[5 * TOPK + k] = (float)(c + 1);
    }
}

// ---------------- launch ----------------
extern "C" void kernel_launch(void* const* d_in, const int* in_sizes, int n_in,
                              void* d_out, int out_size) {
    const float *logits = nullptr, *reg = nullptr, *props = nullptr;
    const void *pw = nullptr, *ph = nullptr;
    for (int i = 0; i < n_in; i++) {
        int s = in_sizes[i];
        if (s == R_N * C_N)            logits = (const float*)d_in[i];
        else if (s == R_N * C_N * 4)   reg    = (const float*)d_in[i];
        else if (s == R_N * 4)         props  = (const float*)d_in[i];
        else if (s == 1) { if (!pw) pw = d_in[i]; else ph = d_in[i]; }
    }
    k_init<<<(NC * R_N + 255) / 256, 256>>>();
    k_decode<<<(R_N * 32 + 127) / 128, 128>>>(logits, reg, props, pw, ph);
    k_nms<<<NC, 256>>>();
    k_top<<<1, 1024>>>((float*)d_out);
}

// round 2
// speedup vs baseline: 1.9163x; 1.9163x over previous
#include <cuda_runtime.h>

#define R_N 1000
#define C_N 81
#define NC  80          // foreground classes
#define NEGV (-1e9f)
#define SCORE_T 0.05f
#define IOU_T 0.5f
#define TOPK 100

// ---------------- device scratch (no allocations allowed) ----------------
__device__ float g_scores[NC * R_N];                 // [class-1][row] prob
__device__ float g_boxes[NC * R_N * 4];              // [class-1][row][4] clipped xyxy
__device__ unsigned long long g_pool[NC * R_N];      // survivor keys
__device__ int g_count;

// ---------------- helpers ----------------
__device__ __forceinline__ unsigned int ord32(float f) {
    unsigned int u = __float_as_uint(f);
    return (u & 0x80000000u) ? ~u : (u | 0x80000000u);
}
__device__ __forceinline__ float unord32(unsigned int u) {
    unsigned int b = (u & 0x80000000u) ? (u ^ 0x80000000u) : ~u;
    return __uint_as_float(b);
}
__device__ __forceinline__ float load_dim(const void* p) {
    int iv = *(const int*)p;
    if (iv > 0 && iv < 1000000) return (float)iv;   // passed as int
    return *(const float*)p;                         // passed as float
}

// descending bitonic sort over shared u64 array, n = power of two
__device__ void bitonic_desc(unsigned long long* a, int n) {
    for (unsigned int k = 2; k <= (unsigned int)n; k <<= 1) {
        for (unsigned int j = k >> 1; j > 0; j >>= 1) {
            for (unsigned int i = threadIdx.x; i < (unsigned int)n; i += blockDim.x) {
                unsigned int l = i ^ j;
                if (l > i) {
                    unsigned long long x = a[i], y = a[l];
                    bool up = ((i & k) == 0);       // descending block
                    if (up ? (x < y) : (x > y)) { a[i] = y; a[l] = x; }
                }
            }
            __syncthreads();
        }
    }
}

// ---------------- kernel 1: softmax + decode + clip ----------------
// one warp per proposal row
__global__ void k_decode(const float* __restrict__ logits,
                         const float* __restrict__ reg,
                         const float* __restrict__ props,
                         const void* pw, const void* ph) {
    int gtid = blockIdx.x * blockDim.x + threadIdx.x;
    if (gtid == 0) g_count = 0;                 // consumed only by later kernels
    int row = gtid >> 5;
    int lane = threadIdx.x & 31;
    if (row >= R_N) return;

    float W = load_dim(pw), H = load_dim(ph);
    const float* lg = logits + (size_t)row * C_N;

    float m = -INFINITY;
    for (int i = lane; i < C_N; i += 32) m = fmaxf(m, lg[i]);
    for (int o = 16; o; o >>= 1) m = fmaxf(m, __shfl_xor_sync(0xffffffffu, m, o));

    float s = 0.f;
    for (int i = lane; i < C_N; i += 32) s += expf(lg[i] - m);
    for (int o = 16; o; o >>= 1) s += __shfl_xor_sync(0xffffffffu, s, o);
    float inv = 1.f / s;

    float px1 = props[row * 4 + 0], py1 = props[row * 4 + 1];
    float px2 = props[row * 4 + 2], py2 = props[row * 4 + 3];
    float bw = px2 - px1 + 1.f, bh = py2 - py1 + 1.f;
    float cx = px1 + 0.5f * bw,  cy = py1 + 0.5f * bh;
    const float CLIPV = 4.135166556742356f;   // log(1000/16)

    for (int c = 1 + lane; c < C_N; c += 32) {
        float prob = expf(lg[c] - m) * inv;
        const float* rr = reg + (size_t)row * (C_N * 4) + 4 * c;
        float dx = rr[0] / 10.0f;
        float dy = rr[1] / 10.0f;
        float dw = fminf(rr[2] / 5.0f, CLIPV);
        float dh = fminf(rr[3] / 5.0f, CLIPV);
        float pcx = dx * bw + cx;
        float pcy = dy * bh + cy;
        float pw2 = expf(dw) * bw;
        float ph2 = expf(dh) * bh;
        float x1 = pcx - 0.5f * pw2;
        float y1 = pcy - 0.5f * ph2;
        float x2 = pcx + 0.5f * pw2 - 1.f;
        float y2 = pcy + 0.5f * ph2 - 1.f;
        x1 = fminf(fmaxf(x1, 0.f), W - 1.f);
        x2 = fminf(fmaxf(x2, 0.f), W - 1.f);
        y1 = fminf(fmaxf(y1, 0.f), H - 1.f);
        y2 = fminf(fmaxf(y2, 0.f), H - 1.f);
        int o = (c - 1) * R_N + row;
        g_scores[o] = prob;
        float* ob = g_boxes + (size_t)o * 4;
        ob[0] = x1; ob[1] = y1; ob[2] = x2; ob[3] = y2;
    }
}

// ---------------- kernel 2: per-class greedy NMS (one block per class) ----------------
__global__ void k_nms() {
    int c = blockIdx.x;
    __shared__ unsigned long long skey[1024];
    __shared__ float sx1[1024], sy1[1024], sx2[1024], sy2[1024], sar[1024];
    __shared__ unsigned char srem[1024];
    __shared__ int sM;
    if (threadIdx.x == 0) sM = 0;
    __syncthreads();

    const float* sc = g_scores + (size_t)c * R_N;
    for (int r = threadIdx.x; r < R_N; r += blockDim.x) {
        float v = sc[r];
        if (v > SCORE_T) {
            int p = atomicAdd(&sM, 1);
            skey[p] = ((unsigned long long)ord32(v) << 32) | (unsigned int)(~r);
        }
    }
    __syncthreads();
    int M = sM;
    if (M == 0) return;

    int n = 1; while (n < M) n <<= 1;
    for (int i = M + threadIdx.x; i < n; i += blockDim.x) skey[i] = 0ULL;
    __syncthreads();
    bitonic_desc(skey, n);   // deterministic (score desc, row asc) order

    for (int i = threadIdx.x; i < M; i += blockDim.x) {
        int r = (int)(~(unsigned int)(skey[i] & 0xffffffffu));
        const float* b = g_boxes + ((size_t)c * R_N + r) * 4;
        float x1 = b[0], y1 = b[1], x2 = b[2], y2 = b[3];
        sx1[i] = x1; sy1[i] = y1; sx2[i] = x2; sy2[i] = y2;
        sar[i] = (x2 - x1 + 1.f) * (y2 - y1 + 1.f);
        srem[i] = 0;
    }
    __syncthreads();

    // greedy suppression in sorted order
    for (int i = 0; i < M; i++) {
        if (!srem[i]) {   // uniform: shared value stable since last barrier
            float X1 = sx1[i], Y1 = sy1[i], X2 = sx2[i], Y2 = sy2[i], A = sar[i];
            for (int j = i + 1 + threadIdx.x; j < M; j += blockDim.x) {
                if (!srem[j]) {
                    float ix1 = fmaxf(X1, sx1[j]), iy1 = fmaxf(Y1, sy1[j]);
                    float ix2 = fminf(X2, sx2[j]), iy2 = fminf(Y2, sy2[j]);
                    float iw = fmaxf(ix2 - ix1 + 1.f, 0.f);
                    float ih = fmaxf(iy2 - iy1 + 1.f, 0.f);
                    float inter = iw * ih;
                    float iou = inter / (A + sar[j] - inter);
                    if (iou > IOU_T) srem[j] = 1;
                }
            }
        }
        __syncthreads();
    }

    for (int i = threadIdx.x; i < M; i += blockDim.x) {
        if (!srem[i]) {
            unsigned long long kk = skey[i];
            int r = (int)(~(unsigned int)(kk & 0xffffffffu));
            unsigned int flat = (unsigned int)(c * R_N + r);
            int p = atomicAdd(&g_count, 1);
            g_pool[p] = (kk & 0xffffffff00000000ULL) | (unsigned int)(~flat);
        }
    }
}

// ---------------- kernel 3: global top-100 via radix select + small sort ----------------
__global__ void k_top(float* __restrict__ out) {
    __shared__ int hist[256];
    __shared__ unsigned long long cand[512];
    __shared__ int s_d, s_cum, s_bin, s_cnt;
    int tid = threadIdx.x;
    int K = g_count;

    if (K <= 256) {
        // small path (also covers K < 100 with deterministic NEG filler)
        int n = 128; while (n < K) n <<= 1;
        for (int i = tid; i < n; i += blockDim.x) cand[i] = (i < K) ? g_pool[i] : 0ULL;
        __syncthreads();
        bitonic_desc(cand, n);
        if (K < TOPK && tid == 0) {
            // top_k tie-break over NEG entries: ascending flat idx, skipping kept ones
            int p = K;
            for (int f = 0; p < TOPK; f++) {
                bool used = false;
                for (int q = 0; q < K; q++) {
                    unsigned int fl = ~(unsigned int)(cand[q] & 0xffffffffu);
                    if ((int)fl == f) { used = true; break; }
                }
                if (!used)
                    cand[p++] = ((unsigned long long)ord32(NEGV) << 32) | (unsigned int)(~f);
            }
        }
        __syncthreads();
    } else {
        // radix-select descent: find 8-bit-digit prefix of the 100th-largest key
        int shift = 56;
        unsigned long long prefix = 0;
        int needed = TOPK;
        for (;;) {
            for (int i = tid; i < 256; i += blockDim.x) hist[i] = 0;
            __syncthreads();
            for (int i = tid; i < K; i += blockDim.x) {
                unsigned long long k = g_pool[i];
                bool act = (shift == 56) || ((k >> (shift + 8)) == prefix);
                if (act) atomicAdd(&hist[(int)((k >> shift) & 255)], 1);
            }
            __syncthreads();
            if (tid == 0) {
                int cum = 0, d;
                for (d = 255; d > 0; d--) {
                    int h = hist[d];
                    if (cum + h >= needed) break;
                    cum += h;
                }
                s_d = d; s_cum = cum; s_bin = hist[d];
            }
            __syncthreads();
            needed -= s_cum;                         // uniform across block
            prefix = (prefix << 8) | (unsigned int)s_d;
            int binCount = s_bin;
            shift -= 8;
            if ((TOPK - needed) + binCount <= 512 || shift < 0) break;
            __syncthreads();                         // hist reused next pass
        }
        // compact all keys >= threshold prefix (count <= 512, keys unique)
        if (tid == 0) s_cnt = 0;
        __syncthreads();
        int sh = shift + 8;                          // 0..56
        for (int i = tid; i < K; i += blockDim.x) {
            unsigned long long k = g_pool[i];
            if ((k >> sh) >= prefix) {
                int p = atomicAdd(&s_cnt, 1);
                if (p < 512) cand[p] = k;
            }
        }
        __syncthreads();
        int count = min(s_cnt, 512);
        int n = 128; while (n < count) n <<= 1;
        for (int i = count + tid; i < n; i += blockDim.x) cand[i] = 0ULL;
        __syncthreads();
        bitonic_desc(cand, n);
    }

    for (int k = tid; k < TOPK; k += blockDim.x) {
        unsigned long long kk = cand[k];
        unsigned int flat = ~(unsigned int)(kk & 0xffffffffu);
        float score = unord32((unsigned int)(kk >> 32));
        int c = flat / R_N;
        const float* b = g_boxes + (size_t)flat * 4;
        out[k] = score;
        out[TOPK + 4 * k + 0] = b[0];
        out[TOPK + 4 * k + 1] = b[1];
        out[TOPK + 4 * k + 2] = b[2];
        out[TOPK + 4 * k + 3] = b[3];
        out[5 * TOPK + k] = (float)(c + 1);
    }
}

// ---------------- launch ----------------
extern "C" void kernel_launch(void* const* d_in, const int* in_sizes, int n_in,
                              void* d_out, int out_size) {
    const float *logits = nullptr, *reg = nullptr, *props = nullptr;
    const void *pw = nullptr, *ph = nullptr;
    for (int i = 0; i < n_in; i++) {
        int s = in_sizes[i];
        if (s == R_N * C_N)            logits = (const float*)d_in[i];
        else if (s == R_N * C_N * 4)   reg    = (const float*)d_in[i];
        else if (s == R_N * 4)         props  = (const float*)d_in[i];
        else if (s == 1) { if (!pw) pw = d_in[i]; else ph = d_in[i]; }
    }
    k_decode<<<(R_N * 32 + 127) / 128, 128>>>(logits, reg, props, pw, ph);
    k_nms<<<NC, 256>>>();
    k_top<<<1, 1024>>>((float*)d_out);
}

// round 3
// speedup vs baseline: 2.1903x; 1.1430x over previous
#include <cuda_runtime.h>

#define R_N 1000
#define C_N 81
#define NC  80          // foreground classes
#define NEGV (-1e9f)
#define SCORE_T 0.05f
#define IOU_T 0.5f
#define TOPK 100
#define GRID 125        // 125 * 8 warps = exactly 1000 rows; all blocks co-resident
#define BLOCK 256

// ---------------- device scratch (no allocations allowed) ----------------
__device__ float g_m[R_N];
__device__ float g_inv[R_N];
__device__ unsigned long long g_pool[NC * R_N];   // survivor keys
__device__ float4 g_pbox[NC * R_N];               // survivor boxes, indexed by flat
__device__ int g_count;
__device__ int g_c1;   // phase-A arrivals
__device__ int g_c2;   // phase-B arrivals

// ---------------- helpers ----------------
__device__ __forceinline__ unsigned int ord32(float f) {
    unsigned int u = __float_as_uint(f);
    return (u & 0x80000000u) ? ~u : (u | 0x80000000u);
}
__device__ __forceinline__ float unord32(unsigned int u) {
    unsigned int b = (u & 0x80000000u) ? (u ^ 0x80000000u) : ~u;
    return __uint_as_float(b);
}
__device__ __forceinline__ float load_dim(const void* p) {
    int iv = *(const int*)p;
    if (iv > 0 && iv < 1000000) return (float)iv;   // passed as int
    return *(const float*)p;                         // passed as float
}

// decode + clip one box (class c in [1,80], row r) — exact reference math
__device__ __forceinline__ float4 decode_box(const float4* __restrict__ props4,
                                             const float4* __restrict__ reg4,
                                             int r, int c, float W, float H) {
    const float CLIPV = 4.135166556742356f;   // log(1000/16)
    float4 p = props4[r];
    float bw = p.z - p.x + 1.f, bh = p.w - p.y + 1.f;
    float cx = p.x + 0.5f * bw,  cy = p.y + 0.5f * bh;
    float4 rr = reg4[(size_t)r * C_N + c];
    float dx = rr.x / 10.0f;
    float dy = rr.y / 10.0f;
    float dw = fminf(rr.z / 5.0f, CLIPV);
    float dh = fminf(rr.w / 5.0f, CLIPV);
    float pcx = dx * bw + cx;
    float pcy = dy * bh + cy;
    float pw2 = expf(dw) * bw;
    float ph2 = expf(dh) * bh;
    float x1 = fminf(fmaxf(pcx - 0.5f * pw2, 0.f), W - 1.f);
    float y1 = fminf(fmaxf(pcy - 0.5f * ph2, 0.f), H - 1.f);
    float x2 = fminf(fmaxf(pcx + 0.5f * pw2 - 1.f, 0.f), W - 1.f);
    float y2 = fminf(fmaxf(pcy + 0.5f * ph2 - 1.f, 0.f), H - 1.f);
    return make_float4(x1, y1, x2, y2);
}

// descending bitonic sort over shared u64 array, n = power of two
__device__ void bitonic_desc(unsigned long long* a, int n) {
    for (unsigned int k = 2; k <= (unsigned int)n; k <<= 1) {
        for (unsigned int j = k >> 1; j > 0; j >>= 1) {
            for (unsigned int i = threadIdx.x; i < (unsigned int)n; i += BLOCK) {
                unsigned int l = i ^ j;
                if (l > i) {
                    unsigned long long x = a[i], y = a[l];
                    bool up = ((i & k) == 0);
                    if (up ? (x < y) : (x > y)) { a[i] = y; a[l] = x; }
                }
            }
            __syncthreads();
        }
    }
}

// ---------------- the single fused kernel ----------------
__global__ void __launch_bounds__(BLOCK) k_fused(
        const float* __restrict__ logits,
        const float* __restrict__ reg,
        const float* __restrict__ props,
        const void* pw, const void* ph,
        float* __restrict__ out) {

    __shared__ unsigned long long skey[1024];
    __shared__ float sx1[1024], sy1[1024], sx2[1024], sy2[1024], sar[1024];
    __shared__ unsigned char srem[1024];
    __shared__ unsigned long long smask[64];
    __shared__ unsigned int s_bal[2];
    __shared__ unsigned long long s_keep;
    __shared__ int sM;
    __shared__ int hist[256];
    __shared__ unsigned long long cand[512];
    __shared__ int s_d, s_cum, s_bin, s_cnt;

    int tid = threadIdx.x;
    int lane = tid & 31;
    const float4* props4 = (const float4*)props;
    const float4* reg4 = (const float4*)reg;
    float W = load_dim(pw), H = load_dim(ph);

    // ---------- Phase A: per-row softmax stats (one warp per row) ----------
    {
        int row = blockIdx.x * (BLOCK / 32) + (tid >> 5);
        if (row < R_N) {
            const float* lg = logits + (size_t)row * C_N;
            float a = (lane      < C_N) ? lg[lane]      : -INFINITY;
            float b = (lane + 32 < C_N) ? lg[lane + 32] : -INFINITY;
            float d = (lane + 64 < C_N) ? lg[lane + 64] : -INFINITY;
            float m = fmaxf(a, fmaxf(b, d));
            for (int o = 16; o; o >>= 1) m = fmaxf(m, __shfl_xor_sync(0xffffffffu, m, o));
            float s = 0.f;
            if (lane      < C_N) s += expf(a - m);
            if (lane + 32 < C_N) s += expf(b - m);
            if (lane + 64 < C_N) s += expf(d - m);
            for (int o = 16; o; o >>= 1) s += __shfl_xor_sync(0xffffffffu, s, o);
            if (lane == 0) { g_m[row] = m; g_inv[row] = 1.f / s; }
        }
    }
    __syncthreads();
    __threadfence();
    if (tid == 0) atomicAdd(&g_c1, 1);
    if (blockIdx.x >= NC) return;          // blocks 80..124: phase A only

    if (tid == 0) { while (*(volatile int*)&g_c1 < GRID) __nanosleep(64); }
    __syncthreads();
    __threadfence();

    // ---------- Phase B: per-class filter + lazy decode + bitmask NMS ----------
    int c = blockIdx.x + 1;                // class index 1..80
    if (tid == 0) sM = 0;
    __syncthreads();
    for (int r = tid; r < R_N; r += BLOCK) {
        float x = __ldg(&logits[(size_t)r * C_N + c]);
        float prob = expf(x - __ldcg(&g_m[r])) * __ldcg(&g_inv[r]);
        if (prob > SCORE_T) {
            int p = atomicAdd(&sM, 1);
            skey[p] = ((unsigned long long)ord32(prob) << 32) | (unsigned int)(~r);
        }
    }
    __syncthreads();
    int M = sM;

    if (M > 0 && M <= 64) {
        // fast path: sort-free bitmask NMS (fixpoint == greedy, keys acyclic)
        unsigned long long mykey = 0ULL;
        float X1 = 0, Y1 = 0, X2 = 0, Y2 = 0, A = 0;
        if (tid < M) {
            mykey = skey[tid];
            int r = (int)(~(unsigned int)mykey);
            float4 b = decode_box(props4, reg4, r, c, W, H);
            X1 = b.x; Y1 = b.y; X2 = b.z; Y2 = b.w;
            A = (X2 - X1 + 1.f) * (Y2 - Y1 + 1.f);
            sx1[tid] = X1; sy1[tid] = Y1; sx2[tid] = X2; sy2[tid] = Y2; sar[tid] = A;
        }
        __syncthreads();
        if (tid < M) {
            unsigned long long msk = 0ULL;
            for (int j = 0; j < M; j++) {
                if (skey[j] > mykey) {
                    float ix1 = fmaxf(X1, sx1[j]), iy1 = fmaxf(Y1, sy1[j]);
                    float ix2 = fminf(X2, sx2[j]), iy2 = fminf(Y2, sy2[j]);
                    float iw = fmaxf(ix2 - ix1 + 1.f, 0.f);
                    float ih = fmaxf(iy2 - iy1 + 1.f, 0.f);
                    float inter = iw * ih;
                    float iou = inter / (A + sar[j] - inter);
                    if (iou > IOU_T) msk |= (1ULL << j);
                }
            }
            smask[tid] = msk;
        }
        unsigned long long full = (M == 64) ? ~0ULL : ((1ULL << M) - 1ULL);
        if (tid == 0) s_keep = full;
        __syncthreads();
        for (int it = 0; it <= M; it++) {
            unsigned long long keep = s_keep;
            bool b = (tid < M) && ((smask[tid] & keep) == 0ULL);
            unsigned int bal = __ballot_sync(0xffffffffu, b);
            if (lane == 0 && tid < 64) s_bal[tid >> 5] = bal;
            __syncthreads();
            unsigned long long nk = (((unsigned long long)s_bal[1] << 32) | s_bal[0]) & full;
            if (nk == keep) break;          // uniform
            __syncthreads();
            if (tid == 0) s_keep = nk;
            __syncthreads();
        }
        unsigned long long keep = s_keep;
        if (tid < M && ((keep >> tid) & 1ULL)) {
            unsigned int r = ~(unsigned int)mykey;
            unsigned int flat = (unsigned int)(blockIdx.x * R_N) + r;
            int p = atomicAdd(&g_count, 1);
            g_pool[p] = (mykey & 0xffffffff00000000ULL) | (unsigned int)(~flat);
            g_pbox[flat] = make_float4(X1, Y1, X2, Y2);
        }
    } else if (M > 64) {
        // fallback: sorted serial greedy (rare)
        int n = 1; while (n < M) n <<= 1;
        for (int i = M + tid; i < n; i += BLOCK) skey[i] = 0ULL;
        __syncthreads();
        bitonic_desc(skey, n);
        for (int i = tid; i < M; i += BLOCK) {
            int r = (int)(~(unsigned int)skey[i]);
            float4 b = decode_box(props4, reg4, r, c, W, H);
            sx1[i] = b.x; sy1[i] = b.y; sx2[i] = b.z; sy2[i] = b.w;
            sar[i] = (b.z - b.x + 1.f) * (b.w - b.y + 1.f);
            srem[i] = 0;
        }
        __syncthreads();
        for (int i = 0; i < M; i++) {
            if (!srem[i]) {
                float X1 = sx1[i], Y1 = sy1[i], X2 = sx2[i], Y2 = sy2[i], A = sar[i];
                for (int j = i + 1 + tid; j < M; j += BLOCK) {
                    if (!srem[j]) {
                        float ix1 = fmaxf(X1, sx1[j]), iy1 = fmaxf(Y1, sy1[j]);
                        float ix2 = fminf(X2, sx2[j]), iy2 = fminf(Y2, sy2[j]);
                        float iw = fmaxf(ix2 - ix1 + 1.f, 0.f);
                        float ih = fmaxf(iy2 - iy1 + 1.f, 0.f);
                        float inter = iw * ih;
                        if (inter / (A + sar[j] - inter) > IOU_T) srem[j] = 1;
                    }
                }
            }
            __syncthreads();
        }
        for (int i = tid; i < M; i += BLOCK) {
            if (!srem[i]) {
                unsigned long long kk = skey[i];
                unsigned int r = ~(unsigned int)kk;
                unsigned int flat = (unsigned int)(blockIdx.x * R_N) + r;
                int p = atomicAdd(&g_count, 1);
                g_pool[p] = (kk & 0xffffffff00000000ULL) | (unsigned int)(~flat);
                g_pbox[flat] = make_float4(sx1[i], sy1[i], sx2[i], sy2[i]);
            }
        }
    }

    __syncthreads();
    __threadfence();
    if (tid == 0) atomicAdd(&g_c2, 1);
    if (blockIdx.x != 0) return;           // only block 0 continues

    if (tid == 0) { while (*(volatile int*)&g_c2 < NC) __nanosleep(64); }
    __syncthreads();
    __threadfence();

    // ---------- Phase C: global top-100 via radix select ----------
    int K = atomicAdd(&g_count, 0);

    if (K <= 256) {
        int n = 128; while (n < K) n <<= 1;
        for (int i = tid; i < n; i += BLOCK) cand[i] = (i < K) ? __ldcg(&g_pool[i]) : 0ULL;
        __syncthreads();
        bitonic_desc(cand, n);
        if (K < TOPK && tid == 0) {
            int p = K;
            for (int f = 0; p < TOPK; f++) {
                bool used = false;
                for (int q = 0; q < K; q++) {
                    unsigned int fl = ~(unsigned int)(cand[q] & 0xffffffffu);
                    if ((int)fl == f) { used = true; break; }
                }
                if (!used)
                    cand[p++] = ((unsigned long long)ord32(NEGV) << 32) | (unsigned int)(~f);
            }
        }
        __syncthreads();
    } else {
        int shift = 56;
        unsigned long long prefix = 0;
        int needed = TOPK;
        for (;;) {
            for (int i = tid; i < 256; i += BLOCK) hist[i] = 0;
            __syncthreads();
            for (int i = tid; i < K; i += BLOCK) {
                unsigned long long k = __ldcg(&g_pool[i]);
                bool act = (shift == 56) || ((k >> (shift + 8)) == prefix);
                if (act) atomicAdd(&hist[(int)((k >> shift) & 255)], 1);
            }
            __syncthreads();
            if (tid == 0) {
                int cum = 0, d;
                for (d = 255; d > 0; d--) {
                    int h = hist[d];
                    if (cum + h >= needed) break;
                    cum += h;
                }
                s_d = d; s_cum = cum; s_bin = hist[d];
            }
            __syncthreads();
            needed -= s_cum;
            prefix = (prefix << 8) | (unsigned int)s_d;
            int binCount = s_bin;
            shift -= 8;
            if ((TOPK - needed) + binCount <= 512 || shift < 0) break;
            __syncthreads();
        }
        if (tid == 0) s_cnt = 0;
        __syncthreads();
        int sh = shift + 8;
        for (int i = tid; i < K; i += BLOCK) {
            unsigned long long k = __ldcg(&g_pool[i]);
            if ((k >> sh) >= prefix) {
                int p = atomicAdd(&s_cnt, 1);
                if (p < 512) cand[p] = k;
            }
        }
        __syncthreads();
        int count = min(s_cnt, 512);
        int n = 128; while (n < count) n <<= 1;
        for (int i = count + tid; i < n; i += BLOCK) cand[i] = 0ULL;
        __syncthreads();
        bitonic_desc(cand, n);
    }

    unsigned int ordneg = ord32(NEGV);
    for (int k = tid; k < TOPK; k += BLOCK) {
        unsigned long long kk = cand[k];
        unsigned int flat = ~(unsigned int)(kk & 0xffffffffu);
        unsigned int so = (unsigned int)(kk >> 32);
        float score = unord32(so);
        int cc = flat / R_N;
        int r = flat - cc * R_N;
        float4 b;
        if (so == ordneg) b = decode_box(props4, reg4, r, cc + 1, W, H);  // filler path
        else              b = __ldcg(&g_pbox[flat]);
        out[k] = score;
        out[TOPK + 4 * k + 0] = b.x;
        out[TOPK + 4 * k + 1] = b.y;
        out[TOPK + 4 * k + 2] = b.z;
        out[TOPK + 4 * k + 3] = b.w;
        out[5 * TOPK + k] = (float)(cc + 1);
    }

    // reset counters for the next graph replay (only block 0 alive here)
    __syncthreads();
    if (tid == 0) { g_c1 = 0; g_c2 = 0; g_count = 0; __threadfence(); }
}

// ---------------- launch ----------------
extern "C" void kernel_launch(void* const* d_in, const int* in_sizes, int n_in,
                              void* d_out, int out_size) {
    const float *logits = nullptr, *reg = nullptr, *props = nullptr;
    const void *pw = nullptr, *ph = nullptr;
    for (int i = 0; i < n_in; i++) {
        int s = in_sizes[i];
        if (s == R_N * C_N)            logits = (const float*)d_in[i];
        else if (s == R_N * C_N * 4)   reg    = (const float*)d_in[i];
        else if (s == R_N * 4)         props  = (const float*)d_in[i];
        else if (s == 1) { if (!pw) pw = d_in[i]; else ph = d_in[i]; }
    }
    k_fused<<<GRID, BLOCK>>>(logits, reg, props, pw, ph, (float*)d_out);
}

// round 5
// speedup vs baseline: 2.7355x; 1.2489x over previous
#include <cuda_runtime.h>

#define R_N 1000
#define C_N 81
#define NC  80          // foreground classes == grid size
#define NEGV (-1e9f)
#define SCORE_T 0.05f
#define IOU_T 0.5f
#define TOPK 100
#define GRID NC
#define BLOCK 256
#define CANDMAX 192

// ---------------- device scratch (no allocations allowed) ----------------
__device__ float g_m[R_N];
__device__ float g_inv[R_N];
__device__ unsigned long long g_pool[NC * R_N];   // survivor keys
__device__ float4 g_pbox[NC * R_N];               // survivor boxes by flat idx
__device__ int g_count;
__device__ int g_c1;   // phase-A arrivals
__device__ int g_c2;   // phase-B ticket

// ---------------- helpers ----------------
__device__ __forceinline__ unsigned int ord32(float f) {
    unsigned int u = __float_as_uint(f);
    return (u & 0x80000000u) ? ~u : (u | 0x80000000u);
}
__device__ __forceinline__ float unord32(unsigned int u) {
    unsigned int b = (u & 0x80000000u) ? (u ^ 0x80000000u) : ~u;
    return __uint_as_float(b);
}
__device__ __forceinline__ float load_dim(const void* p) {
    int iv = *(const int*)p;
    if (iv > 0 && iv < 1000000) return (float)iv;   // passed as int
    return *(const float*)p;                         // passed as float
}

// decode + clip one box (class c in [1,80], row r) — exact reference math
__device__ __forceinline__ float4 decode_box(const float4* __restrict__ props4,
                                             const float4* __restrict__ reg4,
                                             int r, int c, float W, float H) {
    const float CLIPV = 4.135166556742356f;   // log(1000/16)
    float4 p = props4[r];
    float bw = p.z - p.x + 1.f, bh = p.w - p.y + 1.f;
    float cx = p.x + 0.5f * bw,  cy = p.y + 0.5f * bh;
    float4 rr = reg4[(size_t)r * C_N + c];
    float dx = rr.x / 10.0f;
    float dy = rr.y / 10.0f;
    float dw = fminf(rr.z / 5.0f, CLIPV);
    float dh = fminf(rr.w / 5.0f, CLIPV);
    float pcx = dx * bw + cx;
    float pcy = dy * bh + cy;
    float pw2 = expf(dw) * bw;
    float ph2 = expf(dh) * bh;
    float x1 = fminf(fmaxf(pcx - 0.5f * pw2, 0.f), W - 1.f);
    float y1 = fminf(fmaxf(pcy - 0.5f * ph2, 0.f), H - 1.f);
    float x2 = fminf(fmaxf(pcx + 0.5f * pw2 - 1.f, 0.f), W - 1.f);
    float y2 = fminf(fmaxf(pcy + 0.5f * ph2 - 1.f, 0.f), H - 1.f);
    return make_float4(x1, y1, x2, y2);
}

// descending bitonic sort over shared u64 array, n = power of two (fallback only)
__device__ void bitonic_desc(unsigned long long* a, int n) {
    for (unsigned int k = 2; k <= (unsigned int)n; k <<= 1) {
        for (unsigned int j = k >> 1; j > 0; j >>= 1) {
            for (unsigned int i = threadIdx.x; i < (unsigned int)n; i += BLOCK) {
                unsigned int l = i ^ j;
                if (l > i) {
                    unsigned long long x = a[i], y = a[l];
                    bool up = ((i & k) == 0);
                    if (up ? (x < y) : (x > y)) { a[i] = y; a[l] = x; }
                }
            }
            __syncthreads();
        }
    }
}

// ---------------- the single fused kernel ----------------
__global__ void __launch_bounds__(BLOCK) k_fused(
        const float* __restrict__ logits,
        const float* __restrict__ reg,
        const float* __restrict__ props,
        const void* pw, const void* ph,
        float* __restrict__ out) {

    __shared__ unsigned long long skey[1024];   // raw compacted keys / fallback sort
    __shared__ unsigned long long sk2[1024];    // rank-sorted keys; phase-C candidates
    __shared__ float sx1[1024], sy1[1024], sx2[1024], sy2[1024], sar[1024];
    __shared__ unsigned char srem[1024];
    __shared__ unsigned long long smask[64];
    __shared__ unsigned long long s_keep;
    __shared__ int sM;
    __shared__ int hist[256];
    __shared__ int s_d, s_cum, s_bin, s_cnt, s_doC;

    int tid = threadIdx.x;
    int lane = tid & 31;
    const float4* props4 = (const float4*)props;
    const float4* reg4 = (const float4*)reg;
    float W = load_dim(pw), H = load_dim(ph);

    // ---------- Phase A: per-row softmax stats (one warp per row, strided) ----------
    for (int row = blockIdx.x * (BLOCK / 32) + (tid >> 5); row < R_N; row += GRID * (BLOCK / 32)) {
        const float* lg = logits + (size_t)row * C_N;
        float a = (lane      < C_N) ? lg[lane]      : -INFINITY;
        float b = (lane + 32 < C_N) ? lg[lane + 32] : -INFINITY;
        float d = (lane + 64 < C_N) ? lg[lane + 64] : -INFINITY;
        float m = fmaxf(a, fmaxf(b, d));
        for (int o = 16; o; o >>= 1) m = fmaxf(m, __shfl_xor_sync(0xffffffffu, m, o));
        float s = 0.f;
        if (lane      < C_N) s += expf(a - m);
        if (lane + 32 < C_N) s += expf(b - m);
        if (lane + 64 < C_N) s += expf(d - m);
        for (int o = 16; o; o >>= 1) s += __shfl_xor_sync(0xffffffffu, s, o);
        if (lane == 0) { g_m[row] = m; g_inv[row] = 1.f / s; }
    }
    __syncthreads();
    __threadfence();
    if (tid == 0) {
        atomicAdd(&g_c1, 1);
        while (*(volatile int*)&g_c1 < GRID) __nanosleep(32);   // all 80 blocks resident
    }
    __syncthreads();
    __threadfence();

    // ---------- Phase B: per-class filter + lazy decode + barrier-light NMS ----------
    int c = blockIdx.x + 1;                // class index 1..80
    if (tid == 0) sM = 0;
    __syncthreads();
    for (int r = tid; r < R_N; r += BLOCK) {
        float x = __ldg(&logits[(size_t)r * C_N + c]);
        float prob = expf(x - __ldcg(&g_m[r])) * __ldcg(&g_inv[r]);
        if (prob > SCORE_T) {
            int p = atomicAdd(&sM, 1);
            skey[p] = ((unsigned long long)ord32(prob) << 32) | (unsigned int)(~r);
        }
    }
    __syncthreads();
    int M = sM;

    if (M > 0 && M <= 64) {
        // fast path: counting-rank sort + suppressor bitmasks + serial walk
        unsigned long long mykey = 0ULL;
        float4 b;
        float A = 0.f;
        int rank = 0;
        if (tid < M) {
            mykey = skey[tid];
            for (int j = 0; j < M; j++) rank += (skey[j] > mykey);
            int r = (int)(~(unsigned int)mykey);
            b = decode_box(props4, reg4, r, c, W, H);
            A = (b.z - b.x + 1.f) * (b.w - b.y + 1.f);
            sk2[rank] = mykey;
            sx1[rank] = b.x; sy1[rank] = b.y; sx2[rank] = b.z; sy2[rank] = b.w;
            sar[rank] = A;
        }
        __syncthreads();
        if (tid < M) {
            unsigned long long msk = 0ULL;
            for (int j = rank + 1; j < M; j++) {
                float ix1 = fmaxf(b.x, sx1[j]), iy1 = fmaxf(b.y, sy1[j]);
                float ix2 = fminf(b.z, sx2[j]), iy2 = fminf(b.w, sy2[j]);
                float iw = fmaxf(ix2 - ix1 + 1.f, 0.f);
                float ih = fmaxf(iy2 - iy1 + 1.f, 0.f);
                float inter = iw * ih;
                float iou = inter / (A + sar[j] - inter);
                if (iou > IOU_T) msk |= (1ULL << j);
            }
            smask[rank] = msk;
        }
        __syncthreads();
        if (tid == 0) {
            unsigned long long removed = 0ULL, keep = 0ULL;
            for (int i = 0; i < M; i++)
                if (!((removed >> i) & 1ULL)) { keep |= (1ULL << i); removed |= smask[i]; }
            s_keep = keep;
        }
        __syncthreads();
        if (tid < M && ((s_keep >> rank) & 1ULL)) {
            unsigned int r = ~(unsigned int)mykey;
            unsigned int flat = (unsigned int)(blockIdx.x * R_N) + r;
            int p = atomicAdd(&g_count, 1);
            g_pool[p] = (mykey & 0xffffffff00000000ULL) | (unsigned int)(~flat);
            g_pbox[flat] = b;
        }
    } else if (M > 64) {
        // fallback: sorted serial greedy (rare)
        int n = 1; while (n < M) n <<= 1;
        for (int i = M + tid; i < n; i += BLOCK) skey[i] = 0ULL;
        __syncthreads();
        bitonic_desc(skey, n);
        for (int i = tid; i < M; i += BLOCK) {
            int r = (int)(~(unsigned int)skey[i]);
            float4 b = decode_box(props4, reg4, r, c, W, H);
            sx1[i] = b.x; sy1[i] = b.y; sx2[i] = b.z; sy2[i] = b.w;
            sar[i] = (b.z - b.x + 1.f) * (b.w - b.y + 1.f);
            srem[i] = 0;
        }
        __syncthreads();
        for (int i = 0; i < M; i++) {
            if (!srem[i]) {
                float X1 = sx1[i], Y1 = sy1[i], X2 = sx2[i], Y2 = sy2[i], A = sar[i];
                for (int j = i + 1 + tid; j < M; j += BLOCK) {
                    if (!srem[j]) {
                        float ix1 = fmaxf(X1, sx1[j]), iy1 = fmaxf(Y1, sy1[j]);
                        float ix2 = fminf(X2, sx2[j]), iy2 = fminf(Y2, sy2[j]);
                        float iw = fmaxf(ix2 - ix1 + 1.f, 0.f);
                        float ih = fmaxf(iy2 - iy1 + 1.f, 0.f);
                        float inter = iw * ih;
                        if (inter / (A + sar[j] - inter) > IOU_T) srem[j] = 1;
                    }
                }
            }
            __syncthreads();
        }
        for (int i = tid; i < M; i += BLOCK) {
            if (!srem[i]) {
                unsigned long long kk = skey[i];
                unsigned int r = ~(unsigned int)kk;
                unsigned int flat = (unsigned int)(blockIdx.x * R_N) + r;
                int p = atomicAdd(&g_count, 1);
                g_pool[p] = (kk & 0xffffffff00000000ULL) | (unsigned int)(~flat);
                g_pbox[flat] = make_float4(sx1[i], sy1[i], sx2[i], sy2[i]);
            }
        }
    }

    // ---------- ticket: last block to finish B runs phase C ----------
    __syncthreads();
    __threadfence();
    if (tid == 0) {
        int t = atomicAdd(&g_c2, 1);
        s_doC = (t == NC - 1);
    }
    __syncthreads();
    if (!s_doC) return;
    __threadfence();

    // ---------- Phase C: radix select to <=192 candidates, rank placement ----------
    int K = atomicAdd(&g_count, 0);
    unsigned long long prefix = 0;
    int shift = 56, needed = TOPK;
    bool takeAll = (K <= CANDMAX);

    if (!takeAll) {
        for (;;) {
            for (int i = tid; i < 256; i += BLOCK) hist[i] = 0;
            __syncthreads();
            for (int i = tid; i < K; i += BLOCK) {
                unsigned long long k = __ldcg(&g_pool[i]);
                bool act = (shift == 56) || ((k >> (shift + 8)) == prefix);
                if (act) atomicAdd(&hist[(int)((k >> shift) & 255)], 1);
            }
            __syncthreads();
            if (tid == 0) {
                int cum = 0, d;
                for (d = 255; d > 0; d--) {
                    int h = hist[d];
                    if (cum + h >= needed) break;
                    cum += h;
                }
                s_d = d; s_cum = cum; s_bin = hist[d];
            }
            __syncthreads();
            needed -= s_cum;
            prefix = (prefix << 8) | (unsigned int)s_d;
            int binCount = s_bin;
            shift -= 8;
            if ((TOPK - needed) + binCount <= CANDMAX || shift < 0) break;
            __syncthreads();
        }
    }
    if (tid == 0) s_cnt = 0;
    __syncthreads();
    int sh = shift + 8;
    for (int i = tid; i < K; i += BLOCK) {
        unsigned long long k = __ldcg(&g_pool[i]);
        if (takeAll || (k >> sh) >= prefix) {
            int p = atomicAdd(&s_cnt, 1);
            if (p < 1024) sk2[p] = k;
        }
    }
    __syncthreads();
    int count = min(s_cnt, 1024);

    if (tid < count) {
        unsigned long long kk = sk2[tid];
        int rank = 0;
        for (int j = 0; j < count; j++) rank += (sk2[j] > kk);
        if (rank < TOPK) {
            unsigned int flat = ~(unsigned int)(kk & 0xffffffffu);
            float score = unord32((unsigned int)(kk >> 32));
            int cc = flat / R_N;
            float4 b = __ldcg(&g_pbox[flat]);
            out[rank] = score;
            out[TOPK + 4 * rank + 0] = b.x;
            out[TOPK + 4 * rank + 1] = b.y;
            out[TOPK + 4 * rank + 2] = b.z;
            out[TOPK + 4 * rank + 3] = b.w;
            out[5 * TOPK + rank] = (float)(cc + 1);
        }
    }
    __syncthreads();
    if (count < TOPK && tid == 0) {
        // K < 100: fill remaining slots NEG-score, ascending unused flat idx
        int p = count;
        for (int f = 0; p < TOPK; f++) {
            bool used = false;
            for (int q = 0; q < count; q++) {
                unsigned int fl = ~(unsigned int)(sk2[q] & 0xffffffffu);
                if ((int)fl == f) { used = true; break; }
            }
            if (!used) {
                int cc = f / R_N;
                int r = f - cc * R_N;
                float4 b = decode_box(props4, reg4, r, cc + 1, W, H);
                out[p] = NEGV;
                out[TOPK + 4 * p + 0] = b.x;
                out[TOPK + 4 * p + 1] = b.y;
                out[TOPK + 4 * p + 2] = b.z;
                out[TOPK + 4 * p + 3] = b.w;
                out[5 * TOPK + p] = (float)(cc + 1);
                p++;
            }
        }
    }

    // reset counters for the next graph replay (all other blocks already exited)
    __syncthreads();
    if (tid == 0) { g_c1 = 0; g_c2 = 0; g_count = 0; __threadfence(); }
}

// ---------------- launch ----------------
extern "C" void kernel_launch(void* const* d_in, const int* in_sizes, int n_in,
                              void* d_out, int out_size) {
    const float *logits = nullptr, *reg = nullptr, *props = nullptr;
    const void *pw = nullptr, *ph = nullptr;
    for (int i = 0; i < n_in; i++) {
        int s = in_sizes[i];
        if (s == R_N * C_N)            logits = (const float*)d_in[i];
        else if (s == R_N * C_N * 4)   reg    = (const float*)d_in[i];
        else if (s == R_N * 4)         props  = (const float*)d_in[i];
        else if (s == 1) { if (!pw) pw = d_in[i]; else ph = d_in[i]; }
    }
    k_fused<<<GRID, BLOCK>>>(logits, reg, props, pw, ph, (float*)d_out);
}

// round 6
// speedup vs baseline: 2.9424x; 1.0756x over previous
#include <cuda_runtime.h>

#define R_N 1000
#define C_N 81
#define NC  80          // foreground classes == grid size
#define NEGV (-1e9f)
#define SCORE_T 0.05f
#define IOU_T 0.5f
#define TOPK 100
#define GRID NC
#define BLOCK 512
#define CANDMAX 192

// ---------------- device scratch (no allocations allowed) ----------------
__device__ int g_cnt[NC];                          // per-class survivor counts (pre-NMS)
__device__ unsigned long long g_clist[NC * R_N];   // per-class key lists
__device__ unsigned long long g_pool[NC * R_N];    // post-NMS survivor keys
__device__ float4 g_pbox[NC * R_N];                // survivor boxes by flat idx
__device__ int g_count;
__device__ int g_c1;   // phase-A arrivals
__device__ int g_c2;   // phase-B ticket

// ---------------- helpers ----------------
__device__ __forceinline__ unsigned int ord32(float f) {
    unsigned int u = __float_as_uint(f);
    return (u & 0x80000000u) ? ~u : (u | 0x80000000u);
}
__device__ __forceinline__ float unord32(unsigned int u) {
    unsigned int b = (u & 0x80000000u) ? (u ^ 0x80000000u) : ~u;
    return __uint_as_float(b);
}
__device__ __forceinline__ float load_dim(const void* p) {
    int iv = *(const int*)p;
    if (iv > 0 && iv < 1000000) return (float)iv;   // passed as int
    return *(const float*)p;                         // passed as float
}
__device__ __forceinline__ void push_key(int c, int row, float prob) {
    // c in 1..80
    if (prob > SCORE_T) {
        int slot = atomicAdd(&g_cnt[c - 1], 1);
        g_clist[(c - 1) * R_N + slot] =
            ((unsigned long long)ord32(prob) << 32) | (unsigned int)(~row);
    }
}

// decode + clip one box (class c in [1,80], row r) — exact reference math
__device__ __forceinline__ float4 decode_box(const float4* __restrict__ props4,
                                             const float4* __restrict__ reg4,
                                             int r, int c, float W, float H) {
    const float CLIPV = 4.135166556742356f;   // log(1000/16)
    float4 p = props4[r];
    float bw = p.z - p.x + 1.f, bh = p.w - p.y + 1.f;
    float cx = p.x + 0.5f * bw,  cy = p.y + 0.5f * bh;
    float4 rr = reg4[(size_t)r * C_N + c];
    float dx = rr.x / 10.0f;
    float dy = rr.y / 10.0f;
    float dw = fminf(rr.z / 5.0f, CLIPV);
    float dh = fminf(rr.w / 5.0f, CLIPV);
    float pcx = dx * bw + cx;
    float pcy = dy * bh + cy;
    float pw2 = expf(dw) * bw;
    float ph2 = expf(dh) * bh;
    float x1 = fminf(fmaxf(pcx - 0.5f * pw2, 0.f), W - 1.f);
    float y1 = fminf(fmaxf(pcy - 0.5f * ph2, 0.f), H - 1.f);
    float x2 = fminf(fmaxf(pcx + 0.5f * pw2 - 1.f, 0.f), W - 1.f);
    float y2 = fminf(fmaxf(pcy + 0.5f * ph2 - 1.f, 0.f), H - 1.f);
    return make_float4(x1, y1, x2, y2);
}

// descending bitonic sort over shared u64 array, n = power of two (fallback only)
__device__ void bitonic_desc(unsigned long long* a, int n) {
    for (unsigned int k = 2; k <= (unsigned int)n; k <<= 1) {
        for (unsigned int j = k >> 1; j > 0; j >>= 1) {
            for (unsigned int i = threadIdx.x; i < (unsigned int)n; i += BLOCK) {
                unsigned int l = i ^ j;
                if (l > i) {
                    unsigned long long x = a[i], y = a[l];
                    bool up = ((i & k) == 0);
                    if (up ? (x < y) : (x > y)) { a[i] = y; a[l] = x; }
                }
            }
            __syncthreads();
        }
    }
}

// ---------------- the single fused kernel ----------------
__global__ void __launch_bounds__(BLOCK) k_fused(
        const float* __restrict__ logits,
        const float* __restrict__ reg,
        const float* __restrict__ props,
        const void* pw, const void* ph,
        float* __restrict__ out) {

    __shared__ unsigned long long skey[1024];   // staged keys / fallback sort
    __shared__ unsigned long long sk2[1024];    // rank-sorted keys; phase-C candidates
    __shared__ float sx1[1024], sy1[1024], sx2[1024], sy2[1024], sar[1024];
    __shared__ unsigned char srem[1024];
    __shared__ unsigned long long smask[64];
    __shared__ unsigned long long s_keep;
    __shared__ int hist[256];
    __shared__ int s_d, s_cum, s_bin, s_cnt, s_doC;

    int tid = threadIdx.x;
    int lane = tid & 31;
    const float4* props4 = (const float4*)props;
    const float4* reg4 = (const float4*)reg;
    float W = load_dim(pw), H = load_dim(ph);

    // ---------- Phase A: softmax stats + score filter + per-class push ----------
    {
        int row = blockIdx.x * (BLOCK / 32) + (tid >> 5);   // one warp per row
        if (row < R_N) {
            const float* lg = logits + (size_t)row * C_N;
            float a = (lane      < C_N) ? lg[lane]      : -INFINITY;
            float b = (lane + 32 < C_N) ? lg[lane + 32] : -INFINITY;
            float d = (lane + 64 < C_N) ? lg[lane + 64] : -INFINITY;
            float m = fmaxf(a, fmaxf(b, d));
            for (int o = 16; o; o >>= 1) m = fmaxf(m, __shfl_xor_sync(0xffffffffu, m, o));
            float ea = (lane      < C_N) ? expf(a - m) : 0.f;
            float eb = (lane + 32 < C_N) ? expf(b - m) : 0.f;
            float ed = (lane + 64 < C_N) ? expf(d - m) : 0.f;
            float s = ea + eb + ed;
            for (int o = 16; o; o >>= 1) s += __shfl_xor_sync(0xffffffffu, s, o);
            float inv = 1.f / s;
            // classes 1..80: lane l owns logit indices l, l+32, l+64
            if (lane >= 1)  push_key(lane,      row, ea * inv);   // c = 1..31
            push_key(lane + 32, row, eb * inv);                   // c = 32..63
            if (lane <= 16) push_key(lane + 64, row, ed * inv);   // c = 64..80
        }
    }
    __syncthreads();
    __threadfence();
    if (tid == 0) {
        atomicAdd(&g_c1, 1);
        while (*(volatile int*)&g_c1 < GRID) __nanosleep(32);   // all 80 blocks resident
    }
    __syncthreads();
    __threadfence();

    // ---------- Phase B: per-class NMS on the pre-filtered list ----------
    int c0 = blockIdx.x;                 // class-1 index 0..79; class = c0+1
    int c = c0 + 1;
    int M = *(volatile int*)&g_cnt[c0];

    if (M > 0 && M <= 64) {
        // fast path: counting-rank sort + suppressor bitmasks + serial walk
        if (tid < M) skey[tid] = __ldcg(&g_clist[c0 * R_N + tid]);
        __syncthreads();
        unsigned long long mykey = 0ULL;
        float4 b;
        float A = 0.f;
        int rank = 0;
        if (tid < M) {
            mykey = skey[tid];
            for (int j = 0; j < M; j++) rank += (skey[j] > mykey);
            int r = (int)(~(unsigned int)mykey);
            b = decode_box(props4, reg4, r, c, W, H);
            A = (b.z - b.x + 1.f) * (b.w - b.y + 1.f);
            sx1[rank] = b.x; sy1[rank] = b.y; sx2[rank] = b.z; sy2[rank] = b.w;
            sar[rank] = A;
        }
        __syncthreads();
        if (tid < M) {
            unsigned long long msk = 0ULL;
            for (int j = rank + 1; j < M; j++) {
                float ix1 = fmaxf(b.x, sx1[j]), iy1 = fmaxf(b.y, sy1[j]);
                float ix2 = fminf(b.z, sx2[j]), iy2 = fminf(b.w, sy2[j]);
                float iw = fmaxf(ix2 - ix1 + 1.f, 0.f);
                float ih = fmaxf(iy2 - iy1 + 1.f, 0.f);
                float inter = iw * ih;
                float iou = inter / (A + sar[j] - inter);
                if (iou > IOU_T) msk |= (1ULL << j);
            }
            smask[rank] = msk;
        }
        __syncthreads();
        if (tid == 0) {
            unsigned long long removed = 0ULL, keep = 0ULL;
            for (int i = 0; i < M; i++)
                if (!((removed >> i) & 1ULL)) { keep |= (1ULL << i); removed |= smask[i]; }
            s_keep = keep;
        }
        __syncthreads();
        if (tid < M && ((s_keep >> rank) & 1ULL)) {
            unsigned int r = ~(unsigned int)mykey;
            unsigned int flat = (unsigned int)(c0 * R_N) + r;
            int p = atomicAdd(&g_count, 1);
            g_pool[p] = (mykey & 0xffffffff00000000ULL) | (unsigned int)(~flat);
            g_pbox[flat] = b;
        }
    } else if (M > 64) {
        // fallback: sorted serial greedy (rare)
        for (int i = tid; i < M; i += BLOCK) skey[i] = __ldcg(&g_clist[c0 * R_N + i]);
        int n = 1; while (n < M) n <<= 1;
        for (int i = M + tid; i < n; i += BLOCK) skey[i] = 0ULL;
        __syncthreads();
        bitonic_desc(skey, n);
        for (int i = tid; i < M; i += BLOCK) {
            int r = (int)(~(unsigned int)skey[i]);
            float4 b = decode_box(props4, reg4, r, c, W, H);
            sx1[i] = b.x; sy1[i] = b.y; sx2[i] = b.z; sy2[i] = b.w;
            sar[i] = (b.z - b.x + 1.f) * (b.w - b.y + 1.f);
            srem[i] = 0;
        }
        __syncthreads();
        for (int i = 0; i < M; i++) {
            if (!srem[i]) {
                float X1 = sx1[i], Y1 = sy1[i], X2 = sx2[i], Y2 = sy2[i], A = sar[i];
                for (int j = i + 1 + tid; j < M; j += BLOCK) {
                    if (!srem[j]) {
                        float ix1 = fmaxf(X1, sx1[j]), iy1 = fmaxf(Y1, sy1[j]);
                        float ix2 = fminf(X2, sx2[j]), iy2 = fminf(Y2, sy2[j]);
                        float iw = fmaxf(ix2 - ix1 + 1.f, 0.f);
                        float ih = fmaxf(iy2 - iy1 + 1.f, 0.f);
                        float inter = iw * ih;
                        if (inter / (A + sar[j] - inter) > IOU_T) srem[j] = 1;
                    }
                }
            }
            __syncthreads();
        }
        for (int i = tid; i < M; i += BLOCK) {
            if (!srem[i]) {
                unsigned long long kk = skey[i];
                unsigned int r = ~(unsigned int)kk;
                unsigned int flat = (unsigned int)(c0 * R_N) + r;
                int p = atomicAdd(&g_count, 1);
                g_pool[p] = (kk & 0xffffffff00000000ULL) | (unsigned int)(~flat);
                g_pbox[flat] = make_float4(sx1[i], sy1[i], sx2[i], sy2[i]);
            }
        }
    }

    // ---------- ticket: last block to finish B runs phase C ----------
    __syncthreads();
    __threadfence();
    if (tid == 0) {
        int t = atomicAdd(&g_c2, 1);
        s_doC = (t == NC - 1);
    }
    __syncthreads();
    if (!s_doC) return;
    __threadfence();

    // ---------- Phase C: radix select to <=192 candidates, rank placement ----------
    int K = atomicAdd(&g_count, 0);
    unsigned long long prefix = 0;
    int shift = 56, needed = TOPK;
    bool takeAll = (K <= CANDMAX);

    if (!takeAll) {
        for (;;) {
            for (int i = tid; i < 256; i += BLOCK) hist[i] = 0;
            __syncthreads();
            for (int i = tid; i < K; i += BLOCK) {
                unsigned long long k = __ldcg(&g_pool[i]);
                bool act = (shift == 56) || ((k >> (shift + 8)) == prefix);
                if (act) atomicAdd(&hist[(int)((k >> shift) & 255)], 1);
            }
            __syncthreads();
            if (tid == 0) {
                int cum = 0, d;
                for (d = 255; d > 0; d--) {
                    int h = hist[d];
                    if (cum + h >= needed) break;
                    cum += h;
                }
                s_d = d; s_cum = cum; s_bin = hist[d];
            }
            __syncthreads();
            needed -= s_cum;
            prefix = (prefix << 8) | (unsigned int)s_d;
            int binCount = s_bin;
            shift -= 8;
            if ((TOPK - needed) + binCount <= CANDMAX || shift < 0) break;
            __syncthreads();
        }
    }
    if (tid == 0) s_cnt = 0;
    __syncthreads();
    int sh = shift + 8;
    for (int i = tid; i < K; i += BLOCK) {
        unsigned long long k = __ldcg(&g_pool[i]);
        if (takeAll || (k >> sh) >= prefix) {
            int p = atomicAdd(&s_cnt, 1);
            if (p < 1024) sk2[p] = k;
        }
    }
    __syncthreads();
    int count = min(s_cnt, 1024);

    if (tid < count) {
        unsigned long long kk = sk2[tid];
        int rank = 0;
        for (int j = 0; j < count; j++) rank += (sk2[j] > kk);
        if (rank < TOPK) {
            unsigned int flat = ~(unsigned int)(kk & 0xffffffffu);
            float score = unord32((unsigned int)(kk >> 32));
            int cc = flat / R_N;
            float4 b = __ldcg(&g_pbox[flat]);
            out[rank] = score;
            out[TOPK + 4 * rank + 0] = b.x;
            out[TOPK + 4 * rank + 1] = b.y;
            out[TOPK + 4 * rank + 2] = b.z;
            out[TOPK + 4 * rank + 3] = b.w;
            out[5 * TOPK + rank] = (float)(cc + 1);
        }
    }
    __syncthreads();
    if (count < TOPK && tid == 0) {
        // K < 100: fill remaining slots NEG-score, ascending unused flat idx
        int p = count;
        for (int f = 0; p < TOPK; f++) {
            bool used = false;
            for (int q = 0; q < count; q++) {
                unsigned int fl = ~(unsigned int)(sk2[q] & 0xffffffffu);
                if ((int)fl == f) { used = true; break; }
            }
            if (!used) {
                int cc = f / R_N;
                int r = f - cc * R_N;
                float4 b = decode_box(props4, reg4, r, cc + 1, W, H);
                out[p] = NEGV;
                out[TOPK + 4 * p + 0] = b.x;
                out[TOPK + 4 * p + 1] = b.y;
                out[TOPK + 4 * p + 2] = b.z;
                out[TOPK + 4 * p + 3] = b.w;
                out[5 * TOPK + p] = (float)(cc + 1);
                p++;
            }
        }
    }

    // reset counters for the next graph replay (all other blocks already exited)
    __syncthreads();
    if (tid < NC) g_cnt[tid] = 0;
    if (tid == 0) { g_c1 = 0; g_c2 = 0; g_count = 0; }
    __threadfence();
}

// ---------------- launch ----------------
extern "C" void kernel_launch(void* const* d_in, const int* in_sizes, int n_in,
                              void* d_out, int out_size) {
    const float *logits = nullptr, *reg = nullptr, *props = nullptr;
    const void *pw = nullptr, *ph = nullptr;
    for (int i = 0; i < n_in; i++) {
        int s = in_sizes[i];
        if (s == R_N * C_N)            logits = (const float*)d_in[i];
        else if (s == R_N * C_N * 4)   reg    = (const float*)d_in[i];
        else if (s == R_N * 4)         props  = (const float*)d_in[i];
        else if (s == 1) { if (!pw) pw = d_in[i]; else ph = d_in[i]; }
    }
    k_fused<<<GRID, BLOCK>>>(logits, reg, props, pw, ph, (float*)d_out);
}